// round 15
// baseline (speedup 1.0000x reference)
#include <cuda_runtime.h>
#include <math.h>

// signal (32, 1024, 2) f32 interleaved. Per (batch, channel):
//   anded[t] = -|s| - log1p(exp(-2e5|s|))/1e5
//   out[t]   = suffix max of anded  (EV_SCALE=1e9 maxish == hard max to ~1e-9)
//
// grid=64: one CTA per (batch, channel). 128 threads, 8 timesteps/thread
// (4x LDG.128 issued in REVERSE so the suffix chain's first operand lands
// first), 4 warps. Single-channel scan chain, 4-warp barrier, 3-load
// predicate-free padded smem carry. Warp-uniform MUFU fast path (corr==0
// exactly when |c| > 4.37e-4, expf underflow).
//
// Best-measured configuration (R12): dur_us 5.952, kernel 4.32us.
// Kernel is launch-overhead bound: DRAM 0.8%, all pipes <2%.

static constexpr int T = 1024;
static constexpr int B = 32;
static constexpr int THREADS = 128;
static constexpr int NWARP = THREADS / 32;   // 4

__device__ __forceinline__ float corr_of(float a) {
    return __logf(1.0f + __expf(-200000.0f * a)) * 1e-5f;
}

__global__ __launch_bounds__(THREADS)
void suffix_robustness_kernel(const float4* __restrict__ signal,
                              float* __restrict__ out) {
    __shared__ float tot[2 * NWARP];

    const int b    = blockIdx.x;         // batch
    const int ch   = blockIdx.y;         // channel 0/1
    const int t    = threadIdx.x;        // thread handles timesteps 8t..8t+7
    const int lane = t & 31;
    const int wid  = t >> 5;

    // Pad totals [NWARP, 2*NWARP) with -INF (covered by the barrier below).
    if (t >= NWARP && t < 2 * NWARP) tot[t] = -INFINITY;

    // signal row b: 2048 floats = 512 float4. Each float4 = 2 timesteps of
    // both channels. Thread t reads float4 indices 4t..4t+3 (ts 8t..8t+7).
    // Issue in reverse: the suffix chain consumes p3's values first.
    const float4* row = signal + b * (T * 2 / 4) + 4 * t;
    float4 p3 = row[3];
    float4 p2 = row[2];
    float4 p1 = row[1];
    float4 p0 = row[0];

    float a7 = fabsf(ch ? p3.w : p3.z);
    float a6 = fabsf(ch ? p3.y : p3.x);
    float a5 = fabsf(ch ? p2.w : p2.z);
    float a4 = fabsf(ch ? p2.y : p2.x);
    float a3 = fabsf(ch ? p1.w : p1.z);
    float a2 = fabsf(ch ? p1.y : p1.x);
    float a1 = fabsf(ch ? p0.w : p0.z);
    float a0 = fabsf(ch ? p0.y : p0.x);

    float amin = fminf(fminf(fminf(a0, a1), fminf(a2, a3)),
                       fminf(fminf(a4, a5), fminf(a6, a7)));

    // Common path: plain negation (valid for both branches' starting point).
    a0 = -a0;  a1 = -a1;  a2 = -a2;  a3 = -a3;
    a4 = -a4;  a5 = -a5;  a6 = -a6;  a7 = -a7;

    // Rare path: subtract correction (corr(|c|)==0 exactly when |c|>4.37e-4).
    if (__ballot_sync(0xffffffffu, amin < 4.5e-4f)) {
        a0 -= corr_of(-a0);  a1 -= corr_of(-a1);
        a2 -= corr_of(-a2);  a3 -= corr_of(-a3);
        a4 -= corr_of(-a4);  a5 -= corr_of(-a5);
        a6 -= corr_of(-a6);  a7 -= corr_of(-a7);
    }

    // Per-thread suffix max: a_i = max(a_i .. a_7)
    a6 = fmaxf(a6, a7);
    a5 = fmaxf(a5, a6);
    a4 = fmaxf(a4, a5);
    a3 = fmaxf(a3, a4);
    a2 = fmaxf(a2, a3);
    a1 = fmaxf(a1, a2);
    a0 = fmaxf(a0, a1);

    // Warp suffix-inclusive scan of thread totals.
    // shfl_down past lane 31 returns own value == identity for max.
    float s = a0;
    #pragma unroll
    for (int off = 1; off < 32; off <<= 1) {
        float o = __shfl_down_sync(0xffffffffu, s, off);
        s = fmaxf(s, o);
    }
    // Carry from later threads in this warp = scan value at lane+1.
    float c = __shfl_down_sync(0xffffffffu, s, 1);
    if (lane == 31) c = -INFINITY;

    // Publish warp total (scan value at lane 0).
    if (lane == 0) tot[wid] = s;

    // Hoist store base off the post-barrier critical path.
    // Output: (final, final_2) concatenated, each (32,1024) row-major.
    float4* o_out = (float4*)(out + ch * (B * T) + b * T) + 2 * t;

    __syncthreads();

    // Predicate-free carry from later warps: 3 pipelined broadcast LDS loads
    // (padding supplies -INF past warp 3), then a 2-level tree max.
    {
        float x1 = tot[wid + 1], x2 = tot[wid + 2], x3 = tot[wid + 3];
        c = fmaxf(c, fmaxf(fmaxf(x1, x2), x3));
    }

    float4 o4a, o4b;
    o4a.x = fmaxf(a0, c);
    o4a.y = fmaxf(a1, c);
    o4a.z = fmaxf(a2, c);
    o4a.w = fmaxf(a3, c);
    o4b.x = fmaxf(a4, c);
    o4b.y = fmaxf(a5, c);
    o4b.z = fmaxf(a6, c);
    o4b.w = fmaxf(a7, c);
    o_out[0] = o4a;
    o_out[1] = o4b;
}

extern "C" void kernel_launch(void* const* d_in, const int* in_sizes, int n_in,
                              void* d_out, int out_size) {
    const float4* signal = (const float4*)d_in[0];
    float* out = (float*)d_out;
    dim3 grid(B, 2);
    suffix_robustness_kernel<<<grid, THREADS>>>(signal, out);
}

// round 16
// speedup vs baseline: 1.0207x; 1.0207x over previous
#include <cuda_runtime.h>
#include <math.h>

// signal (32, 1024, 2) f32 interleaved. Per (batch, channel):
//   anded[t] = -|s| - log1p(exp(-2e5|s|))/1e5
//   out[t]   = suffix max of anded  (EV_SCALE=1e9 maxish == hard max to ~1e-9)
//
// FINAL (R12 configuration; best recorded dur_us 5.952, kernel 4.32us).
// grid=64: one CTA per (batch, channel). 128 threads, 8 timesteps/thread
// (4x LDG.128 issued in REVERSE so the suffix chain's first operand lands
// first), 4 warps. Single-channel scan chain, 4-warp barrier, 3-load
// predicate-free padded smem carry. Warp-uniform MUFU fast path (corr==0
// exactly when |c| > 4.37e-4, expf underflow).
//
// Kernel is launch-overhead bound: DRAM <1%, all pipes <2%; measured
// run-to-run noise on identical code is +/-0.35us.

static constexpr int T = 1024;
static constexpr int B = 32;
static constexpr int THREADS = 128;
static constexpr int NWARP = THREADS / 32;   // 4

__device__ __forceinline__ float corr_of(float a) {
    return __logf(1.0f + __expf(-200000.0f * a)) * 1e-5f;
}

__global__ __launch_bounds__(THREADS)
void suffix_robustness_kernel(const float4* __restrict__ signal,
                              float* __restrict__ out) {
    __shared__ float tot[2 * NWARP];

    const int b    = blockIdx.x;         // batch
    const int ch   = blockIdx.y;         // channel 0/1
    const int t    = threadIdx.x;        // thread handles timesteps 8t..8t+7
    const int lane = t & 31;
    const int wid  = t >> 5;

    // Pad totals [NWARP, 2*NWARP) with -INF (covered by the barrier below).
    if (t >= NWARP && t < 2 * NWARP) tot[t] = -INFINITY;

    // signal row b: 2048 floats = 512 float4. Each float4 = 2 timesteps of
    // both channels. Thread t reads float4 indices 4t..4t+3 (ts 8t..8t+7).
    // Issue in reverse: the suffix chain consumes p3's values first.
    const float4* row = signal + b * (T * 2 / 4) + 4 * t;
    float4 p3 = row[3];
    float4 p2 = row[2];
    float4 p1 = row[1];
    float4 p0 = row[0];

    float a7 = fabsf(ch ? p3.w : p3.z);
    float a6 = fabsf(ch ? p3.y : p3.x);
    float a5 = fabsf(ch ? p2.w : p2.z);
    float a4 = fabsf(ch ? p2.y : p2.x);
    float a3 = fabsf(ch ? p1.w : p1.z);
    float a2 = fabsf(ch ? p1.y : p1.x);
    float a1 = fabsf(ch ? p0.w : p0.z);
    float a0 = fabsf(ch ? p0.y : p0.x);

    float amin = fminf(fminf(fminf(a0, a1), fminf(a2, a3)),
                       fminf(fminf(a4, a5), fminf(a6, a7)));

    // Common path: plain negation (valid for both branches' starting point).
    a0 = -a0;  a1 = -a1;  a2 = -a2;  a3 = -a3;
    a4 = -a4;  a5 = -a5;  a6 = -a6;  a7 = -a7;

    // Rare path: subtract correction (corr(|c|)==0 exactly when |c|>4.37e-4).
    if (__ballot_sync(0xffffffffu, amin < 4.5e-4f)) {
        a0 -= corr_of(-a0);  a1 -= corr_of(-a1);
        a2 -= corr_of(-a2);  a3 -= corr_of(-a3);
        a4 -= corr_of(-a4);  a5 -= corr_of(-a5);
        a6 -= corr_of(-a6);  a7 -= corr_of(-a7);
    }

    // Per-thread suffix max: a_i = max(a_i .. a_7)
    a6 = fmaxf(a6, a7);
    a5 = fmaxf(a5, a6);
    a4 = fmaxf(a4, a5);
    a3 = fmaxf(a3, a4);
    a2 = fmaxf(a2, a3);
    a1 = fmaxf(a1, a2);
    a0 = fmaxf(a0, a1);

    // Warp suffix-inclusive scan of thread totals.
    // shfl_down past lane 31 returns own value == identity for max.
    float s = a0;
    #pragma unroll
    for (int off = 1; off < 32; off <<= 1) {
        float o = __shfl_down_sync(0xffffffffu, s, off);
        s = fmaxf(s, o);
    }
    // Carry from later threads in this warp = scan value at lane+1.
    float c = __shfl_down_sync(0xffffffffu, s, 1);
    if (lane == 31) c = -INFINITY;

    // Publish warp total (scan value at lane 0).
    if (lane == 0) tot[wid] = s;

    // Hoist store base off the post-barrier critical path.
    // Output: (final, final_2) concatenated, each (32,1024) row-major.
    float4* o_out = (float4*)(out + ch * (B * T) + b * T) + 2 * t;

    __syncthreads();

    // Predicate-free carry from later warps: 3 pipelined broadcast LDS loads
    // (padding supplies -INF past warp 3), then a 2-level tree max.
    {
        float x1 = tot[wid + 1], x2 = tot[wid + 2], x3 = tot[wid + 3];
        c = fmaxf(c, fmaxf(fmaxf(x1, x2), x3));
    }

    float4 o4a, o4b;
    o4a.x = fmaxf(a0, c);
    o4a.y = fmaxf(a1, c);
    o4a.z = fmaxf(a2, c);
    o4a.w = fmaxf(a3, c);
    o4b.x = fmaxf(a4, c);
    o4b.y = fmaxf(a5, c);
    o4b.z = fmaxf(a6, c);
    o4b.w = fmaxf(a7, c);
    o_out[0] = o4a;
    o_out[1] = o4b;
}

extern "C" void kernel_launch(void* const* d_in, const int* in_sizes, int n_in,
                              void* d_out, int out_size) {
    const float4* signal = (const float4*)d_in[0];
    float* out = (float*)d_out;
    dim3 grid(B, 2);
    suffix_robustness_kernel<<<grid, THREADS>>>(signal, out);
}

// round 17
// speedup vs baseline: 1.0260x; 1.0052x over previous
#include <cuda_runtime.h>
#include <math.h>

// signal (32, 1024, 2) f32 interleaved. Per (batch, channel):
//   anded[t] = -|s| - log1p(exp(-2e5|s|))/1e5
//   out[t]   = suffix max of anded  (EV_SCALE=1e9 maxish == hard max to ~1e-9)
//
// FINAL KERNEL (R12 configuration).
// grid=64: one CTA per (batch, channel). 128 threads, 8 timesteps/thread
// (4x LDG.128 issued in REVERSE so the suffix chain's first operand lands
// first), 4 warps. Single-channel scan chain, 4-warp barrier, 3-load
// predicate-free padded smem carry. Warp-uniform MUFU fast path (corr==0
// exactly when |c| > 4.37e-4, expf underflow).
//
// Measured: dur_us 5.95-6.30 (run noise +/-0.35us on identical code),
// kernel 4.32-4.77us, rel_err 6.95e-8. Launch-overhead bound: DRAM <1%,
// all pipes <2% — no saturated resource remains.

static constexpr int T = 1024;
static constexpr int B = 32;
static constexpr int THREADS = 128;
static constexpr int NWARP = THREADS / 32;   // 4

__device__ __forceinline__ float corr_of(float a) {
    return __logf(1.0f + __expf(-200000.0f * a)) * 1e-5f;
}

__global__ __launch_bounds__(THREADS)
void suffix_robustness_kernel(const float4* __restrict__ signal,
                              float* __restrict__ out) {
    __shared__ float tot[2 * NWARP];

    const int b    = blockIdx.x;         // batch
    const int ch   = blockIdx.y;         // channel 0/1
    const int t    = threadIdx.x;        // thread handles timesteps 8t..8t+7
    const int lane = t & 31;
    const int wid  = t >> 5;

    // Pad totals [NWARP, 2*NWARP) with -INF (covered by the barrier below).
    if (t >= NWARP && t < 2 * NWARP) tot[t] = -INFINITY;

    // signal row b: 2048 floats = 512 float4. Each float4 = 2 timesteps of
    // both channels. Thread t reads float4 indices 4t..4t+3 (ts 8t..8t+7).
    // Issue in reverse: the suffix chain consumes p3's values first.
    const float4* row = signal + b * (T * 2 / 4) + 4 * t;
    float4 p3 = row[3];
    float4 p2 = row[2];
    float4 p1 = row[1];
    float4 p0 = row[0];

    float a7 = fabsf(ch ? p3.w : p3.z);
    float a6 = fabsf(ch ? p3.y : p3.x);
    float a5 = fabsf(ch ? p2.w : p2.z);
    float a4 = fabsf(ch ? p2.y : p2.x);
    float a3 = fabsf(ch ? p1.w : p1.z);
    float a2 = fabsf(ch ? p1.y : p1.x);
    float a1 = fabsf(ch ? p0.w : p0.z);
    float a0 = fabsf(ch ? p0.y : p0.x);

    float amin = fminf(fminf(fminf(a0, a1), fminf(a2, a3)),
                       fminf(fminf(a4, a5), fminf(a6, a7)));

    // Common path: plain negation (valid for both branches' starting point).
    a0 = -a0;  a1 = -a1;  a2 = -a2;  a3 = -a3;
    a4 = -a4;  a5 = -a5;  a6 = -a6;  a7 = -a7;

    // Rare path: subtract correction (corr(|c|)==0 exactly when |c|>4.37e-4).
    if (__ballot_sync(0xffffffffu, amin < 4.5e-4f)) {
        a0 -= corr_of(-a0);  a1 -= corr_of(-a1);
        a2 -= corr_of(-a2);  a3 -= corr_of(-a3);
        a4 -= corr_of(-a4);  a5 -= corr_of(-a5);
        a6 -= corr_of(-a6);  a7 -= corr_of(-a7);
    }

    // Per-thread suffix max: a_i = max(a_i .. a_7)
    a6 = fmaxf(a6, a7);
    a5 = fmaxf(a5, a6);
    a4 = fmaxf(a4, a5);
    a3 = fmaxf(a3, a4);
    a2 = fmaxf(a2, a3);
    a1 = fmaxf(a1, a2);
    a0 = fmaxf(a0, a1);

    // Warp suffix-inclusive scan of thread totals.
    // shfl_down past lane 31 returns own value == identity for max.
    float s = a0;
    #pragma unroll
    for (int off = 1; off < 32; off <<= 1) {
        float o = __shfl_down_sync(0xffffffffu, s, off);
        s = fmaxf(s, o);
    }
    // Carry from later threads in this warp = scan value at lane+1.
    float c = __shfl_down_sync(0xffffffffu, s, 1);
    if (lane == 31) c = -INFINITY;

    // Publish warp total (scan value at lane 0).
    if (lane == 0) tot[wid] = s;

    // Hoist store base off the post-barrier critical path.
    // Output: (final, final_2) concatenated, each (32,1024) row-major.
    float4* o_out = (float4*)(out + ch * (B * T) + b * T) + 2 * t;

    __syncthreads();

    // Predicate-free carry from later warps: 3 pipelined broadcast LDS loads
    // (padding supplies -INF past warp 3), then a 2-level tree max.
    {
        float x1 = tot[wid + 1], x2 = tot[wid + 2], x3 = tot[wid + 3];
        c = fmaxf(c, fmaxf(fmaxf(x1, x2), x3));
    }

    float4 o4a, o4b;
    o4a.x = fmaxf(a0, c);
    o4a.y = fmaxf(a1, c);
    o4a.z = fmaxf(a2, c);
    o4a.w = fmaxf(a3, c);
    o4b.x = fmaxf(a4, c);
    o4b.y = fmaxf(a5, c);
    o4b.z = fmaxf(a6, c);
    o4b.w = fmaxf(a7, c);
    o_out[0] = o4a;
    o_out[1] = o4b;
}

extern "C" void kernel_launch(void* const* d_in, const int* in_sizes, int n_in,
                              void* d_out, int out_size) {
    const float4* signal = (const float4*)d_in[0];
    float* out = (float*)d_out;
    dim3 grid(B, 2);
    suffix_robustness_kernel<<<grid, THREADS>>>(signal, out);
}